// round 14
// baseline (speedup 1.0000x reference)
#include <cuda_runtime.h>
#include <cuda_bf16.h>

// PreProcesser: backbone frames + electrostatic field voxel divergence.
// Z*N=512 residues, A=14 atoms, 16^3 voxels, RES=1, X_LBL=20.
// Output: C_backbone (512*12) | divergence (512*4096) | frames (512*9).
//
// R14 (= R10 resubmit; repeated infra timeouts): line-per-thread. Each thread
// computes one full x-line (16 voxels, fixed y,v) and differences in a
// 2-register streaming window. 131072 threads -> ONE wave at 64 regs
// (8x128 blocks/SM). No sS smem, no field/diff barriers, incremental
// voxel positions.

#define A_ 14

__device__ __forceinline__ float frsqrt_approx(float x) {
    float r; asm("rsqrt.approx.f32 %0, %1;" : "=f"(r) : "f"(x)); return r;
}

__global__ __launch_bounds__(128, 8)
void preproc_kernel(const float* __restrict__ C,
                    const int*   __restrict__ L32,
                    const float* __restrict__ atom_mask,
                    const float* __restrict__ amber,
                    float* __restrict__ out,
                    int zn)
{
    float* out_cb  = out;                          // zn*12
    float* out_div = out + (size_t)zn * 12;        // zn*4096
    float* out_fr  = out_div + (size_t)zn * 4096;  // zn*9

    __shared__ float4 sAtom[A_];     // (ax, ay, az, charge)
    __shared__ float  sFrm[12];      // x_unit, y_unit, z_unit, origin(=cb)
    __shared__ int    sLc;

    const int res  = blockIdx.x >> 1;
    const int half = blockIdx.x & 1;       // y in [half*8, half*8+8)
    const int y0   = half << 3;
    const int tid  = threadIdx.x;          // 128 threads = 128 (y,v) lines

    // ---- label dtype detection, parallel across warp 1 (tids 32..63) ----
    // If L is int64 (little endian), every odd 32-bit word is the high word of
    // a value in [-1, 21) -> must be 0 or -1. 32 lanes x 8 odd words = 256.
    if (tid >= 32 && tid < 64) {
        int lane = tid - 32;
        bool ok = true;
        #pragma unroll
        for (int j = 0; j < 8; j++) {
            int v = L32[1 + 2 * (lane * 8 + j)];   // reads <= index 511: safe either way
            ok &= (v == 0) | (v == -1);
        }
        bool all64 = __all_sync(0xffffffffu, ok);
        if (lane == 0) {
            long long l = all64 ? ((const long long*)L32)[res]
                                : (long long)L32[res];
            sLc = (l == -1) ? 20 : (int)l;         // X_LBL = 20
        }
    }

    // ---- per-residue backbone + frames (thread 0; gmem writes from half 0) ----
    if (tid == 0) {
        const float* Cr = C + (size_t)res * (A_ * 3);
        float nx=Cr[0],  ny=Cr[1],  nz=Cr[2];
        float cax=Cr[3], cay=Cr[4], caz=Cr[5];
        float cx=Cr[6],  cy=Cr[7],  cz=Cr[8];

        float b1x=cax-nx,  b1y=cay-ny,  b1z=caz-nz;
        float b2x=cx-cax,  b2y=cy-cay,  b2z=cz-caz;
        float b3x=b1y*b2z-b1z*b2y;
        float b3y=b1z*b2x-b1x*b2z;
        float b3z=b1x*b2y-b1y*b2x;
        float cbx = cax - 0.58273431f*b2x + 0.56802827f*b1x - 0.54067466f*b3x;
        float cby = cay - 0.58273431f*b2y + 0.56802827f*b1y - 0.54067466f*b3y;
        float cbz = caz - 0.58273431f*b2z + 0.56802827f*b1z - 0.54067466f*b3z;

        // y = cb - ca
        float yx=cbx-cax, yy=cby-cay, yz=cbz-caz;
        float yn = sqrtf(yx*yx + yy*yy + yz*yz);
        float yd = fmaxf(yn, 1e-6f);
        float yux=yx/yd, yuy=yy/yd, yuz=yz/yd;

        // x_raw = c - n; reference subtracts the SCALAR projection from every
        // component (bug-compatible).
        float xrx=cx-nx, xry=cy-ny, xrz=cz-nz;
        float xp = xrx*yux + xry*yuy + xrz*yuz;
        float xx=xrx-xp, xy=xry-xp, xz=xrz-xp;
        float xn = sqrtf(xx*xx + xy*xy + xz*xz);
        float xd = fmaxf(xn, 1e-6f);
        float xux=xx/xd, xuy=xy/xd, xuz=xz/xd;

        float zux = xuy*yuz - xuz*yuy;
        float zuy = xuz*yux - xux*yuz;
        float zuz = xux*yuy - xuy*yux;

        if (half == 0) {
            float* cbp = out_cb + (size_t)res * 12;
            cbp[0]=nx;  cbp[1]=ny;  cbp[2]=nz;
            cbp[3]=cax; cbp[4]=cay; cbp[5]=caz;
            cbp[6]=cx;  cbp[7]=cy;  cbp[8]=cz;
            cbp[9]=cbx; cbp[10]=cby; cbp[11]=cbz;

            float* frp = out_fr + (size_t)res * 9;
            frp[0]=xux; frp[1]=xuy; frp[2]=xuz;
            frp[3]=yux; frp[4]=yuy; frp[5]=yuz;
            frp[6]=zux; frp[7]=zuy; frp[8]=zuz;
        }

        sFrm[0]=xux; sFrm[1]=xuy; sFrm[2]=xuz;
        sFrm[3]=yux; sFrm[4]=yuy; sFrm[5]=yuz;
        sFrm[6]=zux; sFrm[7]=zuy; sFrm[8]=zuz;
        sFrm[9]=cbx; sFrm[10]=cby; sFrm[11]=cbz;   // origin = cb
    }
    __syncthreads();

    if (tid < A_) {
        const float* Cr = C + (size_t)res * (A_ * 3) + tid * 3;
        float q = amber[sLc * A_ + tid] * atom_mask[(size_t)res * A_ + tid];
        sAtom[tid] = make_float4(Cr[0], Cr[1], Cr[2], q);
    }
    __syncthreads();

    const float xux=sFrm[0], xuy=sFrm[1], xuz=sFrm[2];
    const float yux=sFrm[3], yuy=sFrm[4], yuz=sFrm[5];
    const float zux=sFrm[6], zuy=sFrm[7], zuz=sFrm[8];
    const float ox =sFrm[9], oy =sFrm[10], oz =sFrm[11];

    // ---- this thread's x-line: (y,v) fixed, x = 0..15 ----
    const int yy = tid >> 4;               // 0..7
    const int v  = tid & 15;               // 0..15
    const float gy = (float)(y0 + yy) - 4.0f;
    const float gz = (float)v - 8.0f;

    // position at x=0 (gx = -8); incremented by x_unit per step
    float px = fmaf(-8.0f, xux, fmaf(gy, yux, fmaf(gz, zux, ox)));
    float py = fmaf(-8.0f, xuy, fmaf(gy, yuy, fmaf(gz, zuy, oy)));
    float pz = fmaf(-8.0f, xuz, fmaf(gy, yuz, fmaf(gz, zuz, oz)));

    // output base for this line
    float* od = out_div + (size_t)res * 4096 + ((y0 + yy) << 4) + v;

    // streaming x-differencing: s1 = S[x-1], s2 = S[x-2]
    float s1 = 0.f, s2 = 0.f, fx14 = 0.f, fxl = 0.f;

    #pragma unroll 4
    for (int x = 0; x < 16; x++) {
        float fx=0.f, fy=0.f, fz=0.f;
        #pragma unroll
        for (int a = 0; a < A_; a++) {
            float4 at = sAtom[a];
            float dx = px - at.x, dy = py - at.y, dz = pz - at.z;
            float d2 = fmaf(dz, dz, fmaf(dy, dy, dx * dx));
            d2 = fmaxf(d2, 1e-12f);
            float r = frsqrt_approx(d2);
            // factor: d>=1 -> 1/d^3, d<1 -> 1/d  ==  r * min(r^2, 1)
            // at d==0 (clamped): dx=dy=dz=0 so contribution is exactly 0.
            float f = (r * at.w) * fminf(r * r, 1.0f);
            fx = fmaf(dx, f, fx);
            fy = fmaf(dy, f, fy);
            fz = fmaf(dz, f, fz);
        }

        // normalize field (zero vector stays zero: numerators are 0)
        float fn2 = fmaf(fx, fx, fmaf(fy, fy, fz * fz));
        float rn = frsqrt_approx(fmaxf(fn2, 1e-30f));
        fx *= rn; fy *= rn; fz *= rn;

        float S = fx + fy + fz;

        // divergence: all three components differenced along voxel-x,
        // with sign flips for y/z handled at the last plane (after loop).
        if (x == 1)      od[0]            = S - s1;          // d0 = S1 - S0
        else if (x >= 2) od[(x - 1) << 8] = 0.5f * (S - s2); // d[x-1]
        if (x == 14) fx14 = fx;
        fxl = fx;                                            // ends as fx15

        s2 = s1; s1 = S;
        px += xux; py += xuy; pz += xuz;
    }
    // d15 = (fx15-fx14) + (fy14-fy15) + (fz14-fz15) = 2*(fx15-fx14) + S14 - S15
    od[15 << 8] = 2.0f * (fxl - fx14) + s2 - s1;
}

extern "C" void kernel_launch(void* const* d_in, const int* in_sizes, int n_in,
                              void* d_out, int out_size) {
    const float* C     = (const float*)d_in[0];   // (Z,N,14,3) f32
    const int*   L     = (const int*)d_in[1];     // (Z,N) int64-or-int32 (auto-detected)
    const float* amask = (const float*)d_in[2];   // (Z,N,14) f32
    // d_in[3] = valid_mask (unused by reference)
    const float* amber = (const float*)d_in[4];   // (21,14) f32
    int zn = in_sizes[1];                         // Z*N = 512
    preproc_kernel<<<zn * 2, 128>>>(C, L, amask, amber, (float*)d_out, zn);
}

// round 16
// speedup vs baseline: 1.1454x; 1.1454x over previous
#include <cuda_runtime.h>
#include <cuda_bf16.h>

// PreProcesser: backbone frames + electrostatic field voxel divergence.
// Z*N=512 residues, A=14 atoms, 16^3 voxels, RES=1, X_LBL=20.
// Output: C_backbone (512*12) | divergence (512*4096) | frames (512*9).
//
// R16 (= R15 resubmit; infra timeout): half-line-per-thread. Keeps R9's
// proven launch shape (1024 x 256, 4 blocks/SM, 32 warps) but streams 8
// x-steps per thread with a 2-register differencing window; the d7/d8
// boundary crosses via ONE warp shuffle (partner = lane^16). No sS smem,
// no post-field barrier, no epilogue loop, incremental voxel positions.

#define A_ 14

__device__ __forceinline__ float frsqrt_approx(float x) {
    float r; asm("rsqrt.approx.f32 %0, %1;" : "=f"(r) : "f"(x)); return r;
}

__global__ __launch_bounds__(256, 4)
void preproc_kernel(const float* __restrict__ C,
                    const int*   __restrict__ L32,
                    const float* __restrict__ atom_mask,
                    const float* __restrict__ amber,
                    float* __restrict__ out,
                    int zn)
{
    float* out_cb  = out;                          // zn*12
    float* out_div = out + (size_t)zn * 12;        // zn*4096
    float* out_fr  = out_div + (size_t)zn * 4096;  // zn*9

    __shared__ float4 sAtom[A_];     // (ax, ay, az, charge)
    __shared__ float  sFrm[12];      // x_unit, y_unit, z_unit, origin(=cb)
    __shared__ int    sLc;

    const int res  = blockIdx.x >> 1;
    const int half = blockIdx.x & 1;       // y in [half*8, half*8+8)
    const int y0   = half << 3;
    const int tid  = threadIdx.x;

    // ---- label dtype detection, parallel across warp 1 (tids 32..63) ----
    // If L is int64 (little endian), every odd 32-bit word is the high word of
    // a value in [-1, 21) -> must be 0 or -1. 32 lanes x 8 odd words = 256.
    if (tid >= 32 && tid < 64) {
        int lane = tid - 32;
        bool ok = true;
        #pragma unroll
        for (int j = 0; j < 8; j++) {
            int v = L32[1 + 2 * (lane * 8 + j)];   // reads <= index 511: safe either way
            ok &= (v == 0) | (v == -1);
        }
        bool all64 = __all_sync(0xffffffffu, ok);
        if (lane == 0) {
            long long l = all64 ? ((const long long*)L32)[res]
                                : (long long)L32[res];
            sLc = (l == -1) ? 20 : (int)l;         // X_LBL = 20
        }
    }

    // ---- per-residue backbone + frames (thread 0; gmem writes from half 0) ----
    if (tid == 0) {
        const float* Cr = C + (size_t)res * (A_ * 3);
        float nx=Cr[0],  ny=Cr[1],  nz=Cr[2];
        float cax=Cr[3], cay=Cr[4], caz=Cr[5];
        float cx=Cr[6],  cy=Cr[7],  cz=Cr[8];

        float b1x=cax-nx,  b1y=cay-ny,  b1z=caz-nz;
        float b2x=cx-cax,  b2y=cy-cay,  b2z=cz-caz;
        float b3x=b1y*b2z-b1z*b2y;
        float b3y=b1z*b2x-b1x*b2z;
        float b3z=b1x*b2y-b1y*b2x;
        float cbx = cax - 0.58273431f*b2x + 0.56802827f*b1x - 0.54067466f*b3x;
        float cby = cay - 0.58273431f*b2y + 0.56802827f*b1y - 0.54067466f*b3y;
        float cbz = caz - 0.58273431f*b2z + 0.56802827f*b1z - 0.54067466f*b3z;

        // y = cb - ca
        float yx=cbx-cax, yy=cby-cay, yz=cbz-caz;
        float yn = sqrtf(yx*yx + yy*yy + yz*yz);
        float yd = fmaxf(yn, 1e-6f);
        float yux=yx/yd, yuy=yy/yd, yuz=yz/yd;

        // x_raw = c - n; reference subtracts the SCALAR projection from every
        // component (bug-compatible).
        float xrx=cx-nx, xry=cy-ny, xrz=cz-nz;
        float xp = xrx*yux + xry*yuy + xrz*yuz;
        float xx=xrx-xp, xy=xry-xp, xz=xrz-xp;
        float xn = sqrtf(xx*xx + xy*xy + xz*xz);
        float xd = fmaxf(xn, 1e-6f);
        float xux=xx/xd, xuy=xy/xd, xuz=xz/xd;

        float zux = xuy*yuz - xuz*yuy;
        float zuy = xuz*yux - xux*yuz;
        float zuz = xux*yuy - xuy*yux;

        if (half == 0) {
            float* cbp = out_cb + (size_t)res * 12;
            cbp[0]=nx;  cbp[1]=ny;  cbp[2]=nz;
            cbp[3]=cax; cbp[4]=cay; cbp[5]=caz;
            cbp[6]=cx;  cbp[7]=cy;  cbp[8]=cz;
            cbp[9]=cbx; cbp[10]=cby; cbp[11]=cbz;

            float* frp = out_fr + (size_t)res * 9;
            frp[0]=xux; frp[1]=xuy; frp[2]=xuz;
            frp[3]=yux; frp[4]=yuy; frp[5]=yuz;
            frp[6]=zux; frp[7]=zuy; frp[8]=zuz;
        }

        sFrm[0]=xux; sFrm[1]=xuy; sFrm[2]=xuz;
        sFrm[3]=yux; sFrm[4]=yuy; sFrm[5]=yuz;
        sFrm[6]=zux; sFrm[7]=zuy; sFrm[8]=zuz;
        sFrm[9]=cbx; sFrm[10]=cby; sFrm[11]=cbz;   // origin = cb
    }
    __syncthreads();

    if (tid < A_) {
        const float* Cr = C + (size_t)res * (A_ * 3) + tid * 3;
        float q = amber[sLc * A_ + tid] * atom_mask[(size_t)res * A_ + tid];
        sAtom[tid] = make_float4(Cr[0], Cr[1], Cr[2], q);
    }
    __syncthreads();

    const float xux=sFrm[0], xuy=sFrm[1], xuz=sFrm[2];
    const float yux=sFrm[3], yuy=sFrm[4], yuz=sFrm[5];
    const float zux=sFrm[6], zuy=sFrm[7], zuz=sFrm[8];
    const float ox =sFrm[9], oy =sFrm[10], oz =sFrm[11];

    // ---- this thread's half-line: (y,v) fixed, x = x0..x0+7 ----
    // layout: yy = tid>>5, xh = (tid>>4)&1, v = tid&15; partner = lane^16
    const int yy = tid >> 5;               // 0..7
    const int xh = (tid >> 4) & 1;         // 0: x=0..7, 1: x=8..15
    const int v  = tid & 15;               // 0..15
    const int x0 = xh << 3;
    const float gy = (float)(y0 + yy) - 4.0f;
    const float gz = (float)v - 8.0f;

    // position at x=x0; incremented by x_unit per step
    const float gx0 = (float)x0 - 8.0f;
    float px = fmaf(gx0, xux, fmaf(gy, yux, fmaf(gz, zux, ox)));
    float py = fmaf(gx0, xuy, fmaf(gy, yuy, fmaf(gz, zuy, oy)));
    float pz = fmaf(gx0, xuz, fmaf(gy, yuz, fmaf(gz, zuz, oz)));

    // output base for this line
    float* od = out_div + (size_t)res * 4096 + ((y0 + yy) << 4) + v;

    // streaming window: s1 = S[x-1], s2 = S[x-2]; extras for boundaries
    float s1 = 0.f, s2 = 0.f;
    float sb0 = 0.f;    // B: S8 (to send to A)
    float sb1 = 0.f;    // B: S9 (for d8)
    float fx14 = 0.f, fxl = 0.f;

    #pragma unroll
    for (int i = 0; i < 8; i++) {
        const int x = x0 + i;
        float fx=0.f, fy=0.f, fz=0.f;
        #pragma unroll
        for (int a = 0; a < A_; a++) {
            float4 at = sAtom[a];
            float dx = px - at.x, dy = py - at.y, dz = pz - at.z;
            float d2 = fmaf(dz, dz, fmaf(dy, dy, dx * dx));
            d2 = fmaxf(d2, 1e-12f);
            float r = frsqrt_approx(d2);
            // factor: d>=1 -> 1/d^3, d<1 -> 1/d  ==  r * min(r^2, 1)
            // at d==0 (clamped): dx=dy=dz=0 so contribution is exactly 0.
            float f = (r * at.w) * fminf(r * r, 1.0f);
            fx = fmaf(dx, f, fx);
            fy = fmaf(dy, f, fy);
            fz = fmaf(dz, f, fz);
        }

        // normalize field (zero vector stays zero: numerators are 0)
        float fn2 = fmaf(fx, fx, fmaf(fy, fy, fz * fz));
        float rn = frsqrt_approx(fmaxf(fn2, 1e-30f));
        fx *= rn; fy *= rn; fz *= rn;

        float S = fx + fy + fz;

        if (xh == 0) {
            // A half: d0 at i==1; d1..d6 streaming
            if (i == 1)      od[0]            = S - s1;
            else if (i >= 2) od[(x - 1) << 8] = 0.5f * (S - s2);
        } else {
            // B half: save S8, S9; d9..d14 streaming
            if (i == 0)      sb0 = S;
            else if (i == 1) sb1 = S;
            if (i >= 2)      od[(x - 1) << 8] = 0.5f * (S - s2);
            if (x == 14) fx14 = fx;
            fxl = fx;                              // ends as fx15
        }

        s2 = s1; s1 = S;
        px += xux; py += xuy; pz += xuz;
    }

    // boundary exchange: A sends S7 (=s1), B sends S8 (=sb0); partner = lane^16
    float sendv = (xh == 0) ? s1 : sb0;
    float recvv = __shfl_xor_sync(0xffffffffu, sendv, 16);
    if (xh == 0) {
        // d7 = 0.5*(S8 - S6)
        od[7 << 8] = 0.5f * (recvv - s2);
    } else {
        // d8 = 0.5*(S9 - S7)
        od[8 << 8] = 0.5f * (sb1 - recvv);
        // d15 = (fx15-fx14) + (fy14-fy15) + (fz14-fz15) = 2*(fx15-fx14) + S14 - S15
        od[15 << 8] = 2.0f * (fxl - fx14) + s2 - s1;
    }
}

extern "C" void kernel_launch(void* const* d_in, const int* in_sizes, int n_in,
                              void* d_out, int out_size) {
    const float* C     = (const float*)d_in[0];   // (Z,N,14,3) f32
    const int*   L     = (const int*)d_in[1];     // (Z,N) int64-or-int32 (auto-detected)
    const float* amask = (const float*)d_in[2];   // (Z,N,14) f32
    // d_in[3] = valid_mask (unused by reference)
    const float* amber = (const float*)d_in[4];   // (21,14) f32
    int zn = in_sizes[1];                         // Z*N = 512
    preproc_kernel<<<zn * 2, 256>>>(C, L, amask, amber, (float*)d_out, zn);
}